// round 6
// baseline (speedup 1.0000x reference)
#include <cuda_runtime.h>

// 3-layer LSTM (H=48) over T=262144 steps, batch 1, + PReLU/Linear/tanh head.
// Single persistent CTA on one SM. All 47k weight elements live in registers
// (384 threads x ~126 floats). h/c recurrence flows through shared memory.
// Matvecs use packed fma.rn.f32x2 (FFMA2). Activations via ex2/rcp.approx,
// distributed across all 192 gate threads (tanh(x) = 2*sigmoid(2x) - 1).

typedef unsigned long long ull;

#define HN    48
#define GATES 192      // 4*HN
#define NT    384      // 12 warps: threads [0,192) = "A" (ih-halves + combine),
                       //           threads [192,384) = "B" (hh-halves + x-proj)

__device__ __forceinline__ void fma2(ull &acc, ull a, ull b) {
    asm("fma.rn.f32x2 %0, %1, %2, %0;" : "+l"(acc) : "l"(a), "l"(b));
}
__device__ __forceinline__ float pairsum(ull a) {
    return __int_as_float((unsigned)a) + __int_as_float((unsigned)(a >> 32));
}
__device__ __forceinline__ ull packf2(float lo, float hi) {
    return (ull)__float_as_uint(lo) | ((ull)__float_as_uint(hi) << 32);
}
// sigmoid(x) = 1/(1+2^(-x*log2(e)))
__device__ __forceinline__ float sigm(float x) {
    float e; asm("ex2.approx.f32 %0, %1;" : "=f"(e) : "f"(-1.4426950408889634f * x));
    float r; asm("rcp.approx.f32 %0, %1;" : "=f"(r) : "f"(1.0f + e));
    return r;
}
// tanh(x) = 1 - 2/(1+e^(2x));   e^(2x) = 2^(x*2*log2(e))
__device__ __forceinline__ float tanh_(float x) {
    float e; asm("ex2.approx.f32 %0, %1;" : "=f"(e) : "f"(2.8853900817779268f * x));
    float r; asm("rcp.approx.f32 %0, %1;" : "=f"(r) : "f"(1.0f + e));
    return fmaf(-2.0f, r, 1.0f);
}

__global__ __launch_bounds__(NT, 1)
void lstm3_kernel(const float* __restrict__ x, int T,
                  const float* __restrict__ Wih0, const float* __restrict__ Whh0,
                  const float* __restrict__ bih0, const float* __restrict__ bhh0,
                  const float* __restrict__ Wih1, const float* __restrict__ Whh1,
                  const float* __restrict__ bih1, const float* __restrict__ bhh1,
                  const float* __restrict__ Wih2, const float* __restrict__ Whh2,
                  const float* __restrict__ bih2, const float* __restrict__ bhh2,
                  const float* __restrict__ prelu_a,
                  const float* __restrict__ l1W, const float* __restrict__ l1b,
                  const float* __restrict__ l2W, const float* __restrict__ l2b,
                  float* __restrict__ out)
{
    __shared__ __align__(16) float s_h[3][HN];   // per-layer hidden state h_{l,t-1}
    __shared__ __align__(16) float s_x[8];       // staged x_t (padded, s_x[5..7]=0)
    __shared__ float s_pb[GATES];                // role-B partial sums
    __shared__ float s_gate[GATES];              // activated gates
    __shared__ float s_bias[3][GATES];           // b_ih + b_hh folded

    const int  tid   = threadIdx.x;
    const bool roleA = (tid < GATES);
    const int  r     = roleA ? tid : tid - GATES;

    // ---- register-resident weights (packed f32x2 pairs) ----
    // roleA thread r: W_hh0[r][0:24), W_ih1[r][:], W_ih2[r][:]
    // roleB thread r: W_hh0[r][24:48), W_ih0[r][:] (x proj), W_hh1[r][:], W_hh2[r][:]
    ull w0[12], wx[3], w1[24], w2[24];
    if (roleA) {
        const ull* p = (const ull*)(Whh0 + r * 48);
        #pragma unroll
        for (int q = 0; q < 12; q++) w0[q] = p[q];
        wx[0] = 0ull; wx[1] = 0ull; wx[2] = 0ull;
        p = (const ull*)(Wih1 + r * 48);
        #pragma unroll
        for (int q = 0; q < 24; q++) w1[q] = p[q];
        p = (const ull*)(Wih2 + r * 48);
        #pragma unroll
        for (int q = 0; q < 24; q++) w2[q] = p[q];
    } else {
        const ull* p = (const ull*)(Whh0 + r * 48 + 24);
        #pragma unroll
        for (int q = 0; q < 12; q++) w0[q] = p[q];
        wx[0] = packf2(Wih0[r * 5 + 0], Wih0[r * 5 + 1]);
        wx[1] = packf2(Wih0[r * 5 + 2], Wih0[r * 5 + 3]);
        wx[2] = packf2(Wih0[r * 5 + 4], 0.0f);
        p = (const ull*)(Whh1 + r * 48);
        #pragma unroll
        for (int q = 0; q < 24; q++) w1[q] = p[q];
        p = (const ull*)(Whh2 + r * 48);
        #pragma unroll
        for (int q = 0; q < 24; q++) w2[q] = p[q];
    }

    // ---- shared init ----
    for (int i = tid; i < 3 * HN; i += NT) (&s_h[0][0])[i] = 0.0f;
    if (roleA) {
        s_bias[0][r] = bih0[r] + bhh0[r];
        s_bias[1][r] = bih1[r] + bhh1[r];
        s_bias[2][r] = bih2[r] + bhh2[r];
    }
    float xnext = 0.0f;
    if (!roleA && r < 8) {
        s_x[r] = (r < 5) ? x[r] : 0.0f;
        if (r < 5) xnext = x[(T > 1 ? 5 : 0) + r];
    }

    // branch-free activation selectors: rows [96,144) are the tanh 'g' gate
    const bool  is_g = roleA && (r >= 96 && r < 144);
    const float aSc  = is_g ? 2.0f : 1.0f;
    const float aMul = is_g ? 2.0f : 1.0f;
    const float aAdd = is_g ? -1.0f : 0.0f;

    float c0 = 0.f, c1 = 0.f, c2 = 0.f;   // cell state, held by threads [0,48)

    const ull* hp0 = ((const ull*)&s_h[0][0]) + (roleA ? 0 : 12);
    const ull* in1 = (const ull*)(roleA ? &s_h[0][0] : &s_h[1][0]);
    const ull* in2 = (const ull*)(roleA ? &s_h[1][0] : &s_h[2][0]);
    const ull* xp  = (const ull*)s_x;

    __syncthreads();

    for (int t = 0; t < T; ++t) {
        // ================= layer 0 =================
        ull a0 = 0ull, a1 = 0ull;
        #pragma unroll
        for (int q = 0; q < 6; q++) {
            ulonglong2 h2 = ((const ulonglong2*)hp0)[q];
            fma2(a0, w0[2 * q],     h2.x);
            fma2(a1, w0[2 * q + 1], h2.y);
        }
        {   // x projection (roleA has zero weights here -> no-op)
            ulonglong2 x2 = ((const ulonglong2*)xp)[0];
            fma2(a0, wx[0], x2.x);
            fma2(a1, wx[1], x2.y);
            fma2(a0, wx[2], xp[2]);
        }
        float part = pairsum(a0) + pairsum(a1);
        if (!roleA) s_pb[r] = part;
        __syncthreads();                                   // B1: partials ready
        if (!roleA && r < 5) {                             // stage x_{t+1}, prefetch x_{t+2}
            s_x[r] = xnext;
            int tn = t + 2; if (tn >= T) tn = T - 1;
            xnext = x[tn * 5 + r];
        }
        if (roleA) {
            float g = part + s_pb[r] + s_bias[0][r];
            float s = sigm(aSc * g);
            s_gate[r] = fmaf(aMul, s, aAdd);
        }
        __syncthreads();                                   // B2: gates ready
        if (tid < HN) {
            float gi = s_gate[tid],        gf = s_gate[HN + tid];
            float gg = s_gate[2 * HN + tid], go = s_gate[3 * HN + tid];
            c0 = fmaf(gf, c0, gi * gg);
            s_h[0][tid] = go * tanh_(c0);
        }
        __syncthreads();                                   // B3: h0_t ready

        // ================= layer 1 =================
        a0 = 0ull; a1 = 0ull;
        #pragma unroll
        for (int q = 0; q < 12; q++) {
            ulonglong2 h2 = ((const ulonglong2*)in1)[q];
            fma2(a0, w1[2 * q],     h2.x);
            fma2(a1, w1[2 * q + 1], h2.y);
        }
        part = pairsum(a0) + pairsum(a1);
        if (!roleA) s_pb[r] = part;
        __syncthreads();                                   // B4
        if (roleA) {
            float g = part + s_pb[r] + s_bias[1][r];
            float s = sigm(aSc * g);
            s_gate[r] = fmaf(aMul, s, aAdd);
        }
        __syncthreads();                                   // B5
        if (tid < HN) {
            float gi = s_gate[tid],        gf = s_gate[HN + tid];
            float gg = s_gate[2 * HN + tid], go = s_gate[3 * HN + tid];
            c1 = fmaf(gf, c1, gi * gg);
            s_h[1][tid] = go * tanh_(c1);
        }
        __syncthreads();                                   // B6: h1_t ready

        // ================= layer 2 =================
        a0 = 0ull; a1 = 0ull;
        #pragma unroll
        for (int q = 0; q < 12; q++) {
            ulonglong2 h2 = ((const ulonglong2*)in2)[q];
            fma2(a0, w2[2 * q],     h2.x);
            fma2(a1, w2[2 * q + 1], h2.y);
        }
        part = pairsum(a0) + pairsum(a1);
        if (!roleA) s_pb[r] = part;
        __syncthreads();                                   // B7
        if (roleA) {
            float g = part + s_pb[r] + s_bias[2][r];
            float s = sigm(aSc * g);
            s_gate[r] = fmaf(aMul, s, aAdd);
        }
        __syncthreads();                                   // B8
        if (tid < HN) {
            float gi = s_gate[tid],        gf = s_gate[HN + tid];
            float gg = s_gate[2 * HN + tid], go = s_gate[3 * HN + tid];
            c2 = fmaf(gf, c2, gi * gg);
            s_h[2][tid] = go * tanh_(c2);
        }
        __syncthreads();                                   // B9: h2_t ready
    }

    // ---- head: PReLU -> lin1 -> flatten -> lin2 -> tanh ----
    if (tid == 0) {
        float a = prelu_a[0];
        float v[6];
        #pragma unroll
        for (int l = 0; l < 3; l++) {
            #pragma unroll
            for (int k = 0; k < 2; k++) {
                float acc = l1b[k];
                #pragma unroll
                for (int j = 0; j < HN; j++) {
                    float hv = s_h[l][j];
                    hv = hv > 0.0f ? hv : a * hv;
                    acc = fmaf(hv, l1W[k * HN + j], acc);
                }
                v[l * 2 + k] = acc;
            }
        }
        #pragma unroll
        for (int k = 0; k < 2; k++) {
            float acc = l2b[k];
            #pragma unroll
            for (int m = 0; m < 6; m++) acc = fmaf(l2W[k * 6 + m], v[m], acc);
            out[k] = tanh_(acc);
        }
    }
}

extern "C" void kernel_launch(void* const* d_in, const int* in_sizes, int n_in,
                              void* d_out, int out_size) {
    int T = in_sizes[0] / 5;   // x is [1, T, 5]
    lstm3_kernel<<<1, NT>>>(
        (const float*)d_in[0], T,
        (const float*)d_in[1],  (const float*)d_in[2],
        (const float*)d_in[3],  (const float*)d_in[4],
        (const float*)d_in[5],  (const float*)d_in[6],
        (const float*)d_in[7],  (const float*)d_in[8],
        (const float*)d_in[9],  (const float*)d_in[10],
        (const float*)d_in[11], (const float*)d_in[12],
        (const float*)d_in[13],
        (const float*)d_in[14], (const float*)d_in[15],
        (const float*)d_in[16], (const float*)d_in[17],
        (float*)d_out);
}

// round 7
// speedup vs baseline: 1.0008x; 1.0008x over previous
#include <cuda_runtime.h>

// 3-layer LSTM (H=48) over T=262144 steps, batch 1, + PReLU/Linear/tanh head.
// Single persistent CTA on one SM. All 47k weight elements live in registers
// (384 threads x ~126 floats). h/c recurrence flows through shared memory.
// Matvecs use packed fma.rn.f32x2 (FFMA2). Activations via ex2/rcp.approx,
// distributed across all 192 gate threads (tanh(x) = 2*sigmoid(2x) - 1).

typedef unsigned long long ull;

#define HN    48
#define GATES 192      // 4*HN
#define NT    384      // 12 warps: threads [0,192) = "A" (ih-halves + combine),
                       //           threads [192,384) = "B" (hh-halves + x-proj)

__device__ __forceinline__ void fma2(ull &acc, ull a, ull b) {
    asm("fma.rn.f32x2 %0, %1, %2, %0;" : "+l"(acc) : "l"(a), "l"(b));
}
__device__ __forceinline__ float pairsum(ull a) {
    return __int_as_float((unsigned)a) + __int_as_float((unsigned)(a >> 32));
}
__device__ __forceinline__ ull packf2(float lo, float hi) {
    return (ull)__float_as_uint(lo) | ((ull)__float_as_uint(hi) << 32);
}
// sigmoid(x) = 1/(1+2^(-x*log2(e)))
__device__ __forceinline__ float sigm(float x) {
    float e; asm("ex2.approx.f32 %0, %1;" : "=f"(e) : "f"(-1.4426950408889634f * x));
    float r; asm("rcp.approx.f32 %0, %1;" : "=f"(r) : "f"(1.0f + e));
    return r;
}
// tanh(x) = 1 - 2/(1+e^(2x));   e^(2x) = 2^(x*2*log2(e))
__device__ __forceinline__ float tanh_(float x) {
    float e; asm("ex2.approx.f32 %0, %1;" : "=f"(e) : "f"(2.8853900817779268f * x));
    float r; asm("rcp.approx.f32 %0, %1;" : "=f"(r) : "f"(1.0f + e));
    return fmaf(-2.0f, r, 1.0f);
}

__global__ __launch_bounds__(NT, 1)
void lstm3_kernel(const float* __restrict__ x, int T,
                  const float* __restrict__ Wih0, const float* __restrict__ Whh0,
                  const float* __restrict__ bih0, const float* __restrict__ bhh0,
                  const float* __restrict__ Wih1, const float* __restrict__ Whh1,
                  const float* __restrict__ bih1, const float* __restrict__ bhh1,
                  const float* __restrict__ Wih2, const float* __restrict__ Whh2,
                  const float* __restrict__ bih2, const float* __restrict__ bhh2,
                  const float* __restrict__ prelu_a,
                  const float* __restrict__ l1W, const float* __restrict__ l1b,
                  const float* __restrict__ l2W, const float* __restrict__ l2b,
                  float* __restrict__ out)
{
    __shared__ __align__(16) float s_h[3][HN];   // per-layer hidden state h_{l,t-1}
    __shared__ __align__(16) float s_x[8];       // staged x_t (padded, s_x[5..7]=0)
    __shared__ float s_pb[GATES];                // role-B partial sums
    __shared__ float s_gate[GATES];              // activated gates
    __shared__ float s_bias[3][GATES];           // b_ih + b_hh folded

    const int  tid   = threadIdx.x;
    const bool roleA = (tid < GATES);
    const int  r     = roleA ? tid : tid - GATES;

    // ---- register-resident weights (packed f32x2 pairs) ----
    // roleA thread r: W_hh0[r][0:24), W_ih1[r][:], W_ih2[r][:]
    // roleB thread r: W_hh0[r][24:48), W_ih0[r][:] (x proj), W_hh1[r][:], W_hh2[r][:]
    ull w0[12], wx[3], w1[24], w2[24];
    if (roleA) {
        const ull* p = (const ull*)(Whh0 + r * 48);
        #pragma unroll
        for (int q = 0; q < 12; q++) w0[q] = p[q];
        wx[0] = 0ull; wx[1] = 0ull; wx[2] = 0ull;
        p = (const ull*)(Wih1 + r * 48);
        #pragma unroll
        for (int q = 0; q < 24; q++) w1[q] = p[q];
        p = (const ull*)(Wih2 + r * 48);
        #pragma unroll
        for (int q = 0; q < 24; q++) w2[q] = p[q];
    } else {
        const ull* p = (const ull*)(Whh0 + r * 48 + 24);
        #pragma unroll
        for (int q = 0; q < 12; q++) w0[q] = p[q];
        wx[0] = packf2(Wih0[r * 5 + 0], Wih0[r * 5 + 1]);
        wx[1] = packf2(Wih0[r * 5 + 2], Wih0[r * 5 + 3]);
        wx[2] = packf2(Wih0[r * 5 + 4], 0.0f);
        p = (const ull*)(Whh1 + r * 48);
        #pragma unroll
        for (int q = 0; q < 24; q++) w1[q] = p[q];
        p = (const ull*)(Whh2 + r * 48);
        #pragma unroll
        for (int q = 0; q < 24; q++) w2[q] = p[q];
    }

    // ---- shared init ----
    for (int i = tid; i < 3 * HN; i += NT) (&s_h[0][0])[i] = 0.0f;
    if (roleA) {
        s_bias[0][r] = bih0[r] + bhh0[r];
        s_bias[1][r] = bih1[r] + bhh1[r];
        s_bias[2][r] = bih2[r] + bhh2[r];
    }
    float xnext = 0.0f;
    if (!roleA && r < 8) {
        s_x[r] = (r < 5) ? x[r] : 0.0f;
        if (r < 5) xnext = x[(T > 1 ? 5 : 0) + r];
    }

    // branch-free activation selectors: rows [96,144) are the tanh 'g' gate
    const bool  is_g = roleA && (r >= 96 && r < 144);
    const float aSc  = is_g ? 2.0f : 1.0f;
    const float aMul = is_g ? 2.0f : 1.0f;
    const float aAdd = is_g ? -1.0f : 0.0f;

    float c0 = 0.f, c1 = 0.f, c2 = 0.f;   // cell state, held by threads [0,48)

    const ull* hp0 = ((const ull*)&s_h[0][0]) + (roleA ? 0 : 12);
    const ull* in1 = (const ull*)(roleA ? &s_h[0][0] : &s_h[1][0]);
    const ull* in2 = (const ull*)(roleA ? &s_h[1][0] : &s_h[2][0]);
    const ull* xp  = (const ull*)s_x;

    __syncthreads();

    for (int t = 0; t < T; ++t) {
        // ================= layer 0 =================
        ull a0 = 0ull, a1 = 0ull;
        #pragma unroll
        for (int q = 0; q < 6; q++) {
            ulonglong2 h2 = ((const ulonglong2*)hp0)[q];
            fma2(a0, w0[2 * q],     h2.x);
            fma2(a1, w0[2 * q + 1], h2.y);
        }
        {   // x projection (roleA has zero weights here -> no-op)
            ulonglong2 x2 = ((const ulonglong2*)xp)[0];
            fma2(a0, wx[0], x2.x);
            fma2(a1, wx[1], x2.y);
            fma2(a0, wx[2], xp[2]);
        }
        float part = pairsum(a0) + pairsum(a1);
        if (!roleA) s_pb[r] = part;
        __syncthreads();                                   // B1: partials ready
        if (!roleA && r < 5) {                             // stage x_{t+1}, prefetch x_{t+2}
            s_x[r] = xnext;
            int tn = t + 2; if (tn >= T) tn = T - 1;
            xnext = x[tn * 5 + r];
        }
        if (roleA) {
            float g = part + s_pb[r] + s_bias[0][r];
            float s = sigm(aSc * g);
            s_gate[r] = fmaf(aMul, s, aAdd);
        }
        __syncthreads();                                   // B2: gates ready
        if (tid < HN) {
            float gi = s_gate[tid],        gf = s_gate[HN + tid];
            float gg = s_gate[2 * HN + tid], go = s_gate[3 * HN + tid];
            c0 = fmaf(gf, c0, gi * gg);
            s_h[0][tid] = go * tanh_(c0);
        }
        __syncthreads();                                   // B3: h0_t ready

        // ================= layer 1 =================
        a0 = 0ull; a1 = 0ull;
        #pragma unroll
        for (int q = 0; q < 12; q++) {
            ulonglong2 h2 = ((const ulonglong2*)in1)[q];
            fma2(a0, w1[2 * q],     h2.x);
            fma2(a1, w1[2 * q + 1], h2.y);
        }
        part = pairsum(a0) + pairsum(a1);
        if (!roleA) s_pb[r] = part;
        __syncthreads();                                   // B4
        if (roleA) {
            float g = part + s_pb[r] + s_bias[1][r];
            float s = sigm(aSc * g);
            s_gate[r] = fmaf(aMul, s, aAdd);
        }
        __syncthreads();                                   // B5
        if (tid < HN) {
            float gi = s_gate[tid],        gf = s_gate[HN + tid];
            float gg = s_gate[2 * HN + tid], go = s_gate[3 * HN + tid];
            c1 = fmaf(gf, c1, gi * gg);
            s_h[1][tid] = go * tanh_(c1);
        }
        __syncthreads();                                   // B6: h1_t ready

        // ================= layer 2 =================
        a0 = 0ull; a1 = 0ull;
        #pragma unroll
        for (int q = 0; q < 12; q++) {
            ulonglong2 h2 = ((const ulonglong2*)in2)[q];
            fma2(a0, w2[2 * q],     h2.x);
            fma2(a1, w2[2 * q + 1], h2.y);
        }
        part = pairsum(a0) + pairsum(a1);
        if (!roleA) s_pb[r] = part;
        __syncthreads();                                   // B7
        if (roleA) {
            float g = part + s_pb[r] + s_bias[2][r];
            float s = sigm(aSc * g);
            s_gate[r] = fmaf(aMul, s, aAdd);
        }
        __syncthreads();                                   // B8
        if (tid < HN) {
            float gi = s_gate[tid],        gf = s_gate[HN + tid];
            float gg = s_gate[2 * HN + tid], go = s_gate[3 * HN + tid];
            c2 = fmaf(gf, c2, gi * gg);
            s_h[2][tid] = go * tanh_(c2);
        }
        __syncthreads();                                   // B9: h2_t ready
    }

    // ---- head: PReLU -> lin1 -> flatten -> lin2 -> tanh ----
    if (tid == 0) {
        float a = prelu_a[0];
        float v[6];
        #pragma unroll
        for (int l = 0; l < 3; l++) {
            #pragma unroll
            for (int k = 0; k < 2; k++) {
                float acc = l1b[k];
                #pragma unroll
                for (int j = 0; j < HN; j++) {
                    float hv = s_h[l][j];
                    hv = hv > 0.0f ? hv : a * hv;
                    acc = fmaf(hv, l1W[k * HN + j], acc);
                }
                v[l * 2 + k] = acc;
            }
        }
        #pragma unroll
        for (int k = 0; k < 2; k++) {
            float acc = l2b[k];
            #pragma unroll
            for (int m = 0; m < 6; m++) acc = fmaf(l2W[k * 6 + m], v[m], acc);
            out[k] = tanh_(acc);
        }
    }
}

extern "C" void kernel_launch(void* const* d_in, const int* in_sizes, int n_in,
                              void* d_out, int out_size) {
    int T = in_sizes[0] / 5;   // x is [1, T, 5]
    lstm3_kernel<<<1, NT>>>(
        (const float*)d_in[0], T,
        (const float*)d_in[1],  (const float*)d_in[2],
        (const float*)d_in[3],  (const float*)d_in[4],
        (const float*)d_in[5],  (const float*)d_in[6],
        (const float*)d_in[7],  (const float*)d_in[8],
        (const float*)d_in[9],  (const float*)d_in[10],
        (const float*)d_in[11], (const float*)d_in[12],
        (const float*)d_in[13],
        (const float*)d_in[14], (const float*)d_in[15],
        (const float*)d_in[16], (const float*)d_in[17],
        (float*)d_out);
}